// round 8
// baseline (speedup 1.0000x reference)
#include <cuda_runtime.h>

#define Bn 1024
#define Ln 50
#define Lp 52      // padded row count
#define Dn 64
#define Sn 2
#define XS 68      // row stride (floats) for Lp x D activation arrays (16B-aligned, 4*XS%32==16)
#define SCS 52     // row stride for the padded 52x52 score matrix
#define NT 256
#define NEGV -4294967296.0f   // float(-2**32+1) after fp32 rounding (matches JAX)

// ---- shared memory layout (float offsets) ----
#define O_X     0       // running x                      52*68 = 3536
#define O_B1    3536    // Qx -> Vx -> inputs(lba)
#define O_B2    7072    // Kx -> att
#define O_WS    10608   // scores 52x52 = 2704
#define O_PM    13312   // padding mask (52)
#define O_SCQ   13364   // lba scores / softmax probs (64)
#define O_GLO   13428   // glo (64)
#define O_GFIN  13492   // final glo (64)
#define O_AIE   13556   // dot(ie, w0) per row (56)
#define O_MISC  13612   // scalars (16)
#define SMEM_FLOATS 13628   // 54.5 KB -> 4 CTAs/SM

typedef unsigned long long u64;

// zero-padded 52x52 copies of c1_w / c2_w, built once per launch by prep_kernel
__device__ float g_c1p[Sn][Lp * Lp];
__device__ float g_c2p[Sn][Lp * Lp];
// tile-major transposed D x D weights: [Q0,K0,V0,Q1,K1,V1,Klba,Vlba]
// g_wp[m*1024 + (k4*4+c)*16 + c4] = float4{ W[k4*4+kk][c4*4+c] : kk=0..3 }
__device__ float4 g_wp[8 * 1024];

__global__ void prep_kernel(const float* __restrict__ c1_w, const float* __restrict__ c2_w,
                            const float* __restrict__ Q_sabs, const float* __restrict__ K_sabs,
                            const float* __restrict__ V_sabs,
                            const float* __restrict__ K_lba, const float* __restrict__ V_lba) {
    int i = blockIdx.x * blockDim.x + threadIdx.x;
    if (i < Sn * Lp * Lp) {
        int s = i / (Lp * Lp);
        int rc = i % (Lp * Lp);
        int r = rc / Lp, c = rc % Lp;
        float v1 = (r < Ln && c < Ln) ? c1_w[s * Ln * Ln + r * Ln + c] : 0.0f;
        float v2 = (r < Ln && c < Ln) ? c2_w[s * Ln * Ln + r * Ln + c] : 0.0f;
        g_c1p[s][rc] = v1;
        g_c2p[s][rc] = v2;
    }
    if (i < 8 * 1024) {
        int m = i >> 10, t = i & 1023;
        int c4 = t & 15, kc = t >> 4;
        int c = kc & 3, k4 = kc >> 2;
        int row = c4 * 4 + c;          // output column of W
        const float* W;
        if (m < 6) {
            int s = m / 3, which = m % 3;
            const float* base = (which == 0) ? Q_sabs : (which == 1) ? K_sabs : V_sabs;
            W = base + s * Dn * Dn;
        } else {
            W = (m == 6) ? K_lba : V_lba;
        }
        float4 v;
        v.x = W[(k4 * 4 + 0) * Dn + row];
        v.y = W[(k4 * 4 + 1) * Dn + row];
        v.z = W[(k4 * 4 + 2) * Dn + row];
        v.w = W[(k4 * 4 + 3) * Dn + row];
        g_wp[i] = v;
    }
}

__device__ __forceinline__ void fma2(u64& acc, u64 a, u64 b) {
    asm("fma.rn.f32x2 %0, %1, %2, %0;" : "+l"(acc) : "l"(a), "l"(b));
}
__device__ __forceinline__ float2 unpk(u64 v) {
    unsigned int lo, hi;
    asm("mov.b64 {%0, %1}, %2;" : "=r"(lo), "=r"(hi) : "l"(v));
    return make_float2(__uint_as_float(lo), __uint_as_float(hi));
}

__device__ __forceinline__ float wredsum(float v) {
#pragma unroll
    for (int o = 16; o; o >>= 1) v += __shfl_xor_sync(0xffffffffu, v, o);
    return v;
}
__device__ __forceinline__ float wredmax(float v) {
#pragma unroll
    for (int o = 16; o; o >>= 1) v = fmaxf(v, __shfl_xor_sync(0xffffffffu, v, o));
    return v;
}
__device__ __forceinline__ float sigm(float x) { return 1.0f / (1.0f + expf(-x)); }

// in-place LayerNorm of rows 0..49 (D cols, stride XS); one warp per row
__device__ __forceinline__ void ln_rows(float* m, int warp, int lane) {
    for (int l = warp; l < Ln; l += 8) {
        float v0 = m[l * XS + lane], v1 = m[l * XS + lane + 32];
        float mu = wredsum(v0 + v1) * (1.0f / Dn);
        v0 -= mu; v1 -= mu;
        float var = wredsum(v0 * v0 + v1 * v1) * (1.0f / Dn);
        float inv = rsqrtf(var + 1e-8f);
        m[l * XS + lane] = v0 * inv;
        m[l * XS + lane + 32] = v1 * inv;
    }
}

// 4x4 tile of out = xin(Lp x D smem) @ W, W given as tile-major transposed g_wp block.
// f32x2 packed over the k (reduction) dim: zero broadcast MOVs, coalesced LDG.
__device__ __forceinline__ void gtile_T(float* __restrict__ out, const float* __restrict__ xin,
                                        const float4* __restrict__ wp, int rp, int c4) {
    const float* x0 = xin + rp * 4 * XS;
    const ulonglong2* wb = ((const ulonglong2*)wp) + c4;
    u64 acc[4][4];
#pragma unroll
    for (int j = 0; j < 4; j++)
#pragma unroll
        for (int c = 0; c < 4; c++) acc[j][c] = 0ull;
#pragma unroll 4
    for (int k4 = 0; k4 < 16; k4++) {
        ulonglong2 xv[4];
#pragma unroll
        for (int j = 0; j < 4; j++)
            xv[j] = *(const ulonglong2*)(x0 + j * XS + k4 * 4);
#pragma unroll
        for (int c = 0; c < 4; c++) {
            ulonglong2 wv = __ldg(wb + (k4 * 4 + c) * 16);
#pragma unroll
            for (int j = 0; j < 4; j++) {
                fma2(acc[j][c], xv[j].x, wv.x);
                fma2(acc[j][c], xv[j].y, wv.y);
            }
        }
    }
#pragma unroll
    for (int j = 0; j < 4; j++) {
        float2 p0 = unpk(acc[j][0]), p1 = unpk(acc[j][1]);
        float2 p2 = unpk(acc[j][2]), p3 = unpk(acc[j][3]);
        *(float4*)(out + (rp * 4 + j) * XS + c4 * 4) =
            make_float4(p0.x + p0.y, p1.x + p1.y, p2.x + p2.y, p3.x + p3.y);
    }
}

__device__ __forceinline__ void gemm44_T(float* __restrict__ out, const float* __restrict__ xin,
                                         const float4* __restrict__ wp, int tid) {
    if (tid < 208) gtile_T(out, xin, wp, tid >> 4, tid & 15);
}

// core: acc += A(4 rows GLOBAL, stride Lp, inner 52) x B(52 x D smem, stride XS), cols c4*4..+3
__device__ __forceinline__ void core52g(const float* __restrict__ A0,
                                        const float* __restrict__ Bm, int c4, float a[4][4]) {
#pragma unroll 4
    for (int k4 = 0; k4 < 13; k4++) {
        float4 wv[4];
#pragma unroll
        for (int j = 0; j < 4; j++)
            wv[j] = __ldg((const float4*)(A0 + j * Lp + k4 * 4));
#pragma unroll
        for (int kk = 0; kk < 4; kk++) {
            float4 bv = *(const float4*)(Bm + (k4 * 4 + kk) * XS + c4 * 4);
#pragma unroll
            for (int j = 0; j < 4; j++) {
                float wk = ((const float*)&wv[j])[kk];
                a[j][0] += wk * bv.x; a[j][1] += wk * bv.y;
                a[j][2] += wk * bv.z; a[j][3] += wk * bv.w;
            }
        }
    }
}

// core with A in smem (scores), stride SCS
__device__ __forceinline__ void core52s(const float* __restrict__ A0,
                                        const float* __restrict__ Bm, int c4, float a[4][4]) {
#pragma unroll 4
    for (int k4 = 0; k4 < 13; k4++) {
        float4 wv[4];
#pragma unroll
        for (int j = 0; j < 4; j++)
            wv[j] = *(const float4*)(A0 + j * SCS + k4 * 4);
#pragma unroll
        for (int kk = 0; kk < 4; kk++) {
            float4 bv = *(const float4*)(Bm + (k4 * 4 + kk) * XS + c4 * 4);
#pragma unroll
            for (int j = 0; j < 4; j++) {
                float wk = ((const float*)&wv[j])[kk];
                a[j][0] += wk * bv.x; a[j][1] += wk * bv.y;
                a[j][2] += wk * bv.z; a[j][3] += wk * bv.w;
            }
        }
    }
}

// embed + pos + mask + LN -> dst (rows 0..49)
__device__ __forceinline__ void build_inputs(float* dst, const int* __restrict__ user_items,
                                             const float* __restrict__ item_embedding,
                                             const float* __restrict__ pos_embedding,
                                             const float* s_pm, int b, int warp, int lane) {
    for (int l = warp; l < Ln; l += 8) {
        int idx = user_items[b * Ln + l];
        float v0 = item_embedding[idx * Dn + lane]      + pos_embedding[l * Dn + lane];
        float v1 = item_embedding[idx * Dn + lane + 32] + pos_embedding[l * Dn + lane + 32];
        float pmv = s_pm[l];
        v0 *= pmv; v1 *= pmv;
        float mu = wredsum(v0 + v1) * (1.0f / Dn);
        v0 -= mu; v1 -= mu;
        float var = wredsum(v0 * v0 + v1 * v1) * (1.0f / Dn);
        float inv = rsqrtf(var + 1e-8f);
        dst[l * XS + lane] = v0 * inv;
        dst[l * XS + lane + 32] = v1 * inv;
    }
}

__global__ void __launch_bounds__(NT, 4) fissa_kernel(
    const int* __restrict__ user_items, const int* __restrict__ pos_items,
    const int* __restrict__ neg_items, const float* __restrict__ padding_mask,
    const float* __restrict__ item_embedding, const float* __restrict__ pos_embedding,
    const float* __restrict__ c1_b, const float* __restrict__ c2_b,
    const float* __restrict__ query_item,
    const float* __restrict__ l1_w, const float* __restrict__ l1_b,
    const float* __restrict__ l2_w, const float* __restrict__ l2_b,
    const float* __restrict__ gated_weight, const float* __restrict__ gated_bias,
    float* __restrict__ out)
{
    extern __shared__ float sm[];
    float* s_x   = sm + O_X;
    float* s_b1  = sm + O_B1;
    float* s_b2  = sm + O_B2;
    float* s_sc  = sm + O_WS;
    float* s_pm  = sm + O_PM;
    float* s_scq = sm + O_SCQ;
    float* s_glo = sm + O_GLO;
    float* s_gf  = sm + O_GFIN;
    float* s_aie = sm + O_AIE;
    float* s_ms  = sm + O_MISC;

    const int b = blockIdx.x;
    const int tid = threadIdx.x;
    const int lane = tid & 31;
    const int warp = tid >> 5;

    if (tid < Lp)  s_pm[tid] = (tid < Ln) ? padding_mask[b * Ln + tid] : 0.0f;
    // zero padded rows 50,51 of x
    if (tid < 2 * XS) s_x[Ln * XS + tid] = 0.0f;
    __syncthreads();

    build_inputs(s_x, user_items, item_embedding, pos_embedding, s_pm, b, warp, lane);
    __syncthreads();

    // ---- transformer layers ----
    for (int s = 0; s < Sn; s++) {
        const float4* wpQ = g_wp + (s * 3 + 0) * 1024;
        const float4* wpK = g_wp + (s * 3 + 1) * 1024;
        const float4* wpV = g_wp + (s * 3 + 2) * 1024;

        // Qx -> b1 and Kx -> b2 in one merged phase (416 tiles over 256 threads)
        for (int t = tid; t < 416; t += NT) {
            if (t < 208) gtile_T(s_b1, s_x, wpQ, t >> 4, t & 15);
            else { int u = t - 208; gtile_T(s_b2, s_x, wpK, u >> 4, u & 15); }
        }
        __syncthreads();

        // scores[q][k] = dot(Qx[q],Kx[k])/8, causal/key mask, * pm[q] -> ws
        // f32x2 packed over d (reduction)
        if (tid < 169) {
            int qp = tid / 13, kr = tid % 13;
            const float* Q0 = s_b1 + qp * 4 * XS;
            const float* K0 = s_b2 + kr * XS;
            u64 acc[4][4];
#pragma unroll
            for (int j = 0; j < 4; j++)
#pragma unroll
                for (int m = 0; m < 4; m++) acc[j][m] = 0ull;
#pragma unroll 4
            for (int d4 = 0; d4 < 16; d4++) {
                ulonglong2 qv[4];
#pragma unroll
                for (int j = 0; j < 4; j++)
                    qv[j] = *(const ulonglong2*)(Q0 + j * XS + d4 * 4);
#pragma unroll
                for (int m = 0; m < 4; m++) {
                    ulonglong2 kv = *(const ulonglong2*)(K0 + m * 13 * XS + d4 * 4);
#pragma unroll
                    for (int j = 0; j < 4; j++) {
                        fma2(acc[j][m], qv[j].x, kv.x);
                        fma2(acc[j][m], qv[j].y, kv.y);
                    }
                }
            }
#pragma unroll
            for (int j = 0; j < 4; j++) {
                int q = qp * 4 + j;
#pragma unroll
                for (int m = 0; m < 4; m++) {
                    int k = kr + 13 * m;
                    float v;
                    if (q >= Ln || k >= Ln) v = 0.0f;
                    else {
                        float2 p = unpk(acc[j][m]);
                        v = (p.x + p.y) * 0.125f;
                        if (k > q) v = NEGV;
                        if (s_pm[k] == 0.0f) v = NEGV;
                        v *= s_pm[q];
                    }
                    s_sc[q * SCS + k] = v;
                }
            }
        }
        __syncthreads();

        gemm44_T(s_b1, s_x, wpV, tid);   __syncthreads();  // Vx -> b1 (Qx dead)

        // att = scores @ Vx + x -> b2 (Kx dead), then LN
        if (tid < 208) {
            int rp = tid >> 4, c4 = tid & 15;
            float a[4][4];
#pragma unroll
            for (int j = 0; j < 4; j++)
#pragma unroll
                for (int i = 0; i < 4; i++) a[j][i] = 0.0f;
            core52s(s_sc + rp * 4 * SCS, s_b1, c4, a);
#pragma unroll
            for (int j = 0; j < 4; j++) {
                int l = rp * 4 + j;
                const float* xr = s_x + l * XS + c4 * 4;
                *(float4*)(s_b2 + l * XS + c4 * 4) =
                    make_float4(a[j][0] + xr[0], a[j][1] + xr[1],
                                a[j][2] + xr[2], a[j][3] + xr[3]);
            }
        }
        __syncthreads();
        ln_rows(s_b2, warp, lane);   // att in b2
        __syncthreads();

        // h = relu(c1p @ att + c1_b) -> b1 (c1p global, L1-resident, no staging)
        if (tid < 208) {
            int rp = tid >> 4, c4 = tid & 15;
            float a[4][4];
#pragma unroll
            for (int j = 0; j < 4; j++)
#pragma unroll
                for (int i = 0; i < 4; i++) a[j][i] = 0.0f;
            core52g(g_c1p[s] + rp * 4 * Lp, s_b2, c4, a);
#pragma unroll
            for (int j = 0; j < 4; j++) {
                int l = rp * 4 + j;
                float4 r;
                if (l < Ln) {
                    float bb = __ldg(c1_b + s * Ln + l);
                    r = make_float4(fmaxf(a[j][0] + bb, 0.f), fmaxf(a[j][1] + bb, 0.f),
                                    fmaxf(a[j][2] + bb, 0.f), fmaxf(a[j][3] + bb, 0.f));
                } else r = make_float4(0.f, 0.f, 0.f, 0.f);
                *(float4*)(s_b1 + l * XS + c4 * 4) = r;
            }
        }
        __syncthreads();

        // ff = c2p @ h + c2_b + att, * pm -> x, then LN
        if (tid < 208) {
            int rp = tid >> 4, c4 = tid & 15;
            float a[4][4];
#pragma unroll
            for (int j = 0; j < 4; j++)
#pragma unroll
                for (int i = 0; i < 4; i++) a[j][i] = 0.0f;
            core52g(g_c2p[s] + rp * 4 * Lp, s_b1, c4, a);
#pragma unroll
            for (int j = 0; j < 4; j++) {
                int l = rp * 4 + j;
                float4 r;
                if (l < Ln) {
                    float bb = __ldg(c2_b + s * Ln + l);
                    float pmv = s_pm[l];
                    const float* at = s_b2 + l * XS + c4 * 4;
                    r = make_float4((a[j][0] + bb + at[0]) * pmv, (a[j][1] + bb + at[1]) * pmv,
                                    (a[j][2] + bb + at[2]) * pmv, (a[j][3] + bb + at[3]) * pmv);
                } else r = make_float4(0.f, 0.f, 0.f, 0.f);
                *(float4*)(s_x + l * XS + c4 * 4) = r;
            }
        }
        __syncthreads();
        ln_rows(s_x, warp, lane);
        __syncthreads();
    }

    // ---- rebuild post-LN inputs into b1 (embeddings L2/L1-resident) ----
    if (tid < 2 * XS) s_b1[Ln * XS + tid] = 0.0f;
    __syncthreads();
    build_inputs(s_b1, user_items, item_embedding, pos_embedding, s_pm, b, warp, lane);
    __syncthreads();

    // ---- LBA head ----
    gemm44_T(s_b2, s_b1, g_wp + 6 * 1024, tid);  __syncthreads();   // Kx -> b2

    // sc[l] = dot(query, Kx[l]); key-mask
    {
        float qv0 = __ldg(query_item + lane), qv1 = __ldg(query_item + lane + 32);
        for (int l = warp; l < Ln; l += 8) {
            float r = qv0 * s_b2[l * XS + lane] + qv1 * s_b2[l * XS + lane + 32];
            r = wredsum(r);
            if (s_pm[l] == 0.0f) r = NEGV;
            if (lane == 0) s_scq[l] = r;
        }
    }
    __syncthreads();

    // softmax over L (warp 0)
    if (warp == 0) {
        float v0 = (lane < Ln) ? s_scq[lane] : -3.4e38f;
        float v1 = (lane + 32 < Ln) ? s_scq[lane + 32] : -3.4e38f;
        float m = wredmax(fmaxf(v0, v1));
        float e0 = (lane < Ln) ? expf(v0 - m) : 0.0f;
        float e1 = (lane + 32 < Ln) ? expf(v1 - m) : 0.0f;
        float ssum = wredsum(e0 + e1);
        float inv = 1.0f / ssum;
        if (lane < Ln) s_scq[lane] = e0 * inv;
        if (lane + 32 < Ln) s_scq[lane + 32] = e1 * inv;
    }
    __syncthreads();

    gemm44_T(s_b2, s_b1, g_wp + 7 * 1024, tid);  __syncthreads();   // Vx -> b2 (Kx dead)

    // glo[d] = sum_l p[l] * Vx[l][d]
    if (tid < Dn) {
        float a = 0.0f;
#pragma unroll 5
        for (int l = 0; l < Ln; l++) a += s_scq[l] * s_b2[l * XS + tid];
        s_glo[tid] = a;
    }
    __syncthreads();

    // LN -> MLP -> residual -> LN -> gfin; a_glo = dot(gfin, w1)+bias (warp 0)
    if (warp == 0) {
        float g0 = s_glo[lane], g1 = s_glo[lane + 32];
        float mu = wredsum(g0 + g1) * (1.0f / Dn);
        g0 -= mu; g1 -= mu;
        float var = wredsum(g0 * g0 + g1 * g1) * (1.0f / Dn);
        float inv = rsqrtf(var + 1e-8f);
        g0 *= inv; g1 *= inv;
        float w1v = l1_w[0], b1v = l1_b[0], w2v = l2_w[0], b2v = l2_b[0];
        float h0 = fmaxf(w1v * g0 + b1v, 0.0f);
        float h1 = fmaxf(w1v * g1 + b1v, 0.0f);
        float f0 = w2v * h0 + b2v + g0;
        float f1 = w2v * h1 + b2v + g1;
        mu = wredsum(f0 + f1) * (1.0f / Dn);
        f0 -= mu; f1 -= mu;
        var = wredsum(f0 * f0 + f1 * f1) * (1.0f / Dn);
        inv = rsqrtf(var + 1e-8f);
        f0 *= inv; f1 *= inv;
        s_gf[lane] = f0; s_gf[lane + 32] = f1;
        float r = wredsum(f0 * __ldg(gated_weight + 64 + lane) + f1 * __ldg(gated_weight + 96 + lane));
        if (lane == 0) s_ms[0] = r + gated_bias[0];
    }

    // a_ie[l] = dot(ie_raw[l], w0)
    {
        float gw0 = __ldg(gated_weight + lane), gw32 = __ldg(gated_weight + 32 + lane);
        for (int l = warp; l < Ln; l += 8) {
            int idx = user_items[b * Ln + l];
            float r = item_embedding[idx * Dn + lane] * gw0
                    + item_embedding[idx * Dn + lane + 32] * gw32;
            r = wredsum(r);
            if (lane == 0) s_aie[l] = r;
        }
    }
    __syncthreads();

    // ---- gating + output LN + dot with pos_e / neg_e ----
    float base_glo = s_ms[0];
    float gf0 = s_gf[lane], gf1 = s_gf[lane + 32];
    float gw128 = __ldg(gated_weight + 128 + lane);
    float gw160 = __ldg(gated_weight + 160 + lane);
    for (int l = warp; l < Ln; l += 8) {
        float xv0 = s_x[l * XS + lane], xv1 = s_x[l * XS + lane + 32];
        float pmv = s_pm[l];
        float base = s_aie[l] + base_glo;
#pragma unroll
        for (int br = 0; br < 2; br++) {
            const int* items = br ? neg_items : pos_items;
            int idx = items[b * Ln + l];
            float m0 = item_embedding[idx * Dn + lane];
            float m1 = item_embedding[idx * Dn + lane + 32];
            float dm = wredsum(m0 * gw128 + m1 * gw160);
            float logit = base + dm;
            float g = sigm(sigm(logit));
            float o0 = (xv0 * g + gf0 * (1.0f - g)) * pmv;
            float o1 = (xv1 * g + gf1 * (1.0f - g)) * pmv;
            float mu = wredsum(o0 + o1) * (1.0f / Dn);
            o0 -= mu; o1 -= mu;
            float var = wredsum(o0 * o0 + o1 * o1) * (1.0f / Dn);
            float inv = rsqrtf(var + 1e-8f);
            float r = wredsum((o0 * m0 + o1 * m1) * inv);
            if (lane == 0) out[br * (Bn * Ln) + b * Ln + l] = r;
        }
    }
}

extern "C" void kernel_launch(void* const* d_in, const int* in_sizes, int n_in,
                              void* d_out, int out_size) {
    const int*   user_items     = (const int*)d_in[0];
    const int*   pos_items      = (const int*)d_in[1];
    const int*   neg_items      = (const int*)d_in[2];
    const float* padding_mask   = (const float*)d_in[3];
    const float* item_embedding = (const float*)d_in[4];
    const float* pos_embedding  = (const float*)d_in[5];
    const float* Q_sabs         = (const float*)d_in[6];
    const float* K_sabs         = (const float*)d_in[7];
    const float* V_sabs         = (const float*)d_in[8];
    const float* c1_w           = (const float*)d_in[9];
    const float* c1_b           = (const float*)d_in[10];
    const float* c2_w           = (const float*)d_in[11];
    const float* c2_b           = (const float*)d_in[12];
    const float* query_item     = (const float*)d_in[13];
    const float* K_lba          = (const float*)d_in[14];
    const float* V_lba          = (const float*)d_in[15];
    const float* l1_w           = (const float*)d_in[16];
    const float* l1_b           = (const float*)d_in[17];
    const float* l2_w           = (const float*)d_in[18];
    const float* l2_b           = (const float*)d_in[19];
    const float* gated_weight   = (const float*)d_in[20];
    const float* gated_bias     = (const float*)d_in[21];

    prep_kernel<<<32, 256>>>(c1_w, c2_w, Q_sabs, K_sabs, V_sabs, K_lba, V_lba);

    size_t smem = SMEM_FLOATS * sizeof(float);
    cudaFuncSetAttribute(fissa_kernel, cudaFuncAttributeMaxDynamicSharedMemorySize, (int)smem);
    fissa_kernel<<<Bn, NT, smem>>>(
        user_items, pos_items, neg_items, padding_mask, item_embedding, pos_embedding,
        c1_b, c2_b, query_item, l1_w, l1_b, l2_w, l2_b, gated_weight, gated_bias,
        (float*)d_out);
}

// round 9
// speedup vs baseline: 1.3017x; 1.3017x over previous
#include <cuda_runtime.h>

#define Bn 1024
#define Ln 50
#define Lp 52      // padded row count
#define Dn 64
#define Sn 2
#define XS 68      // row stride (floats) for Lp x D activation arrays (16B-aligned, 4*XS%32==16)
#define SCS 52     // row stride for the padded 52x52 score matrix
#define NT 256
#define NEGV -4294967296.0f   // float(-2**32+1) after fp32 rounding (matches JAX)

// ---- shared memory layout (float offsets) ----
#define O_X     0       // running x                      52*68 = 3536
#define O_B1    3536    // Qx -> Vx -> inputs(lba)
#define O_B2    7072    // Kx -> att
#define O_WS    10608   // scores 52x52 = 2704
#define O_PM    13312   // padding mask (52)
#define O_SCQ   13364   // lba scores / softmax probs (64)
#define O_GLO   13428   // glo (64)
#define O_GFIN  13492   // final glo (64)
#define O_AIE   13556   // dot(ie, w0) per row (56)
#define O_MISC  13612   // scalars (16)
#define SMEM_FLOATS 13628   // 54.5 KB -> 4 CTAs/SM

typedef unsigned long long u64;

// zero-padded 52x52 copies of c1_w / c2_w, built once per launch by prep_kernel
__device__ float g_c1p[Sn][Lp * Lp];
__device__ float g_c2p[Sn][Lp * Lp];

__global__ void prep_kernel(const float* __restrict__ c1_w, const float* __restrict__ c2_w) {
    int i = blockIdx.x * blockDim.x + threadIdx.x;
    if (i < Sn * Lp * Lp) {
        int s = i / (Lp * Lp);
        int rc = i % (Lp * Lp);
        int r = rc / Lp, c = rc % Lp;
        float v1 = (r < Ln && c < Ln) ? c1_w[s * Ln * Ln + r * Ln + c] : 0.0f;
        float v2 = (r < Ln && c < Ln) ? c2_w[s * Ln * Ln + r * Ln + c] : 0.0f;
        g_c1p[s][rc] = v1;
        g_c2p[s][rc] = v2;
    }
}

// packed fp32x2 fma: acc = a*b + acc (each 32-bit half independent, round-to-nearest)
__device__ __forceinline__ void fma2(u64& acc, u64 a, u64 b) {
    asm("fma.rn.f32x2 %0, %1, %2, %0;" : "+l"(acc) : "l"(a), "l"(b));
}
// broadcast one float into both halves of a u64 (alu-pipe MOV, frees fma pipe)
__device__ __forceinline__ u64 bcast(float x) {
    u64 r;
    asm("mov.b64 %0, {%1, %1};" : "=l"(r) : "r"(__float_as_uint(x)));
    return r;
}
__device__ __forceinline__ float2 unpk(u64 v) {
    unsigned int lo, hi;
    asm("mov.b64 {%0, %1}, %2;" : "=r"(lo), "=r"(hi) : "l"(v));
    return make_float2(__uint_as_float(lo), __uint_as_float(hi));
}

__device__ __forceinline__ float wredsum(float v) {
#pragma unroll
    for (int o = 16; o; o >>= 1) v += __shfl_xor_sync(0xffffffffu, v, o);
    return v;
}
__device__ __forceinline__ float wredmax(float v) {
#pragma unroll
    for (int o = 16; o; o >>= 1) v = fmaxf(v, __shfl_xor_sync(0xffffffffu, v, o));
    return v;
}
__device__ __forceinline__ float sigm(float x) { return 1.0f / (1.0f + expf(-x)); }

// in-place LayerNorm of rows 0..49 (D cols, stride XS); one warp per row
__device__ __forceinline__ void ln_rows(float* m, int warp, int lane) {
    for (int l = warp; l < Ln; l += 8) {
        float v0 = m[l * XS + lane], v1 = m[l * XS + lane + 32];
        float mu = wredsum(v0 + v1) * (1.0f / Dn);
        v0 -= mu; v1 -= mu;
        float var = wredsum(v0 * v0 + v1 * v1) * (1.0f / Dn);
        float inv = rsqrtf(var + 1e-8f);
        m[l * XS + lane] = v0 * inv;
        m[l * XS + lane + 32] = v1 * inv;
    }
}

// one 4x4 output tile of out = xin(Lp x D smem, stride XS) @ w(DxD global row-major)
// f32x2 packed over output columns: acc u64[4][2] (16 regs, same as scalar).
__device__ __forceinline__ void gtile(float* __restrict__ out, const float* __restrict__ xin,
                                      const float* __restrict__ w, int rp, int c4) {
    const float* x0 = xin + rp * 4 * XS;
    u64 a[4][2];
#pragma unroll
    for (int j = 0; j < 4; j++) { a[j][0] = 0ull; a[j][1] = 0ull; }
#pragma unroll 4
    for (int k4 = 0; k4 < 16; k4++) {
        float4 xv[4];
#pragma unroll
        for (int j = 0; j < 4; j++)
            xv[j] = *(const float4*)(x0 + j * XS + k4 * 4);
#pragma unroll
        for (int kk = 0; kk < 4; kk++) {
            ulonglong2 wv = __ldg((const ulonglong2*)(w + (k4 * 4 + kk) * Dn + c4 * 4));
#pragma unroll
            for (int j = 0; j < 4; j++) {
                u64 xb = bcast(((const float*)&xv[j])[kk]);
                fma2(a[j][0], xb, wv.x);
                fma2(a[j][1], xb, wv.y);
            }
        }
    }
#pragma unroll
    for (int j = 0; j < 4; j++) {
        float2 p0 = unpk(a[j][0]), p1 = unpk(a[j][1]);
        *(float4*)(out + (rp * 4 + j) * XS + c4 * 4) = make_float4(p0.x, p0.y, p1.x, p1.y);
    }
}

__device__ __forceinline__ void gemm44_xw(float* __restrict__ out, const float* __restrict__ xin,
                                          const float* __restrict__ w, int tid) {
    if (tid < 208) gtile(out, xin, w, tid >> 4, tid & 15);
}

// core: acc += A(4 rows GLOBAL, stride Lp, inner 52) x B(52 x D smem, stride XS), cols c4*4..+3
// f32x2 packed over B columns.
__device__ __forceinline__ void core52g(const float* __restrict__ A0,
                                        const float* __restrict__ Bm, int c4, u64 a[4][2]) {
#pragma unroll 4
    for (int k4 = 0; k4 < 13; k4++) {
        float4 wv[4];
#pragma unroll
        for (int j = 0; j < 4; j++)
            wv[j] = __ldg((const float4*)(A0 + j * Lp + k4 * 4));
#pragma unroll
        for (int kk = 0; kk < 4; kk++) {
            ulonglong2 bv = *(const ulonglong2*)(Bm + (k4 * 4 + kk) * XS + c4 * 4);
#pragma unroll
            for (int j = 0; j < 4; j++) {
                u64 ab = bcast(((const float*)&wv[j])[kk]);
                fma2(a[j][0], ab, bv.x);
                fma2(a[j][1], ab, bv.y);
            }
        }
    }
}

// core with A in smem (scores), stride SCS
__device__ __forceinline__ void core52s(const float* __restrict__ A0,
                                        const float* __restrict__ Bm, int c4, u64 a[4][2]) {
#pragma unroll 4
    for (int k4 = 0; k4 < 13; k4++) {
        float4 wv[4];
#pragma unroll
        for (int j = 0; j < 4; j++)
            wv[j] = *(const float4*)(A0 + j * SCS + k4 * 4);
#pragma unroll
        for (int kk = 0; kk < 4; kk++) {
            ulonglong2 bv = *(const ulonglong2*)(Bm + (k4 * 4 + kk) * XS + c4 * 4);
#pragma unroll
            for (int j = 0; j < 4; j++) {
                u64 ab = bcast(((const float*)&wv[j])[kk]);
                fma2(a[j][0], ab, bv.x);
                fma2(a[j][1], ab, bv.y);
            }
        }
    }
}

// embed + pos + mask + LN -> dst (rows 0..49)
__device__ __forceinline__ void build_inputs(float* dst, const int* __restrict__ user_items,
                                             const float* __restrict__ item_embedding,
                                             const float* __restrict__ pos_embedding,
                                             const float* s_pm, int b, int warp, int lane) {
    for (int l = warp; l < Ln; l += 8) {
        int idx = user_items[b * Ln + l];
        float v0 = item_embedding[idx * Dn + lane]      + pos_embedding[l * Dn + lane];
        float v1 = item_embedding[idx * Dn + lane + 32] + pos_embedding[l * Dn + lane + 32];
        float pmv = s_pm[l];
        v0 *= pmv; v1 *= pmv;
        float mu = wredsum(v0 + v1) * (1.0f / Dn);
        v0 -= mu; v1 -= mu;
        float var = wredsum(v0 * v0 + v1 * v1) * (1.0f / Dn);
        float inv = rsqrtf(var + 1e-8f);
        dst[l * XS + lane] = v0 * inv;
        dst[l * XS + lane + 32] = v1 * inv;
    }
}

__global__ void __launch_bounds__(NT, 4) fissa_kernel(
    const int* __restrict__ user_items, const int* __restrict__ pos_items,
    const int* __restrict__ neg_items, const float* __restrict__ padding_mask,
    const float* __restrict__ item_embedding, const float* __restrict__ pos_embedding,
    const float* __restrict__ Q_sabs, const float* __restrict__ K_sabs,
    const float* __restrict__ V_sabs,
    const float* __restrict__ c1_b, const float* __restrict__ c2_b,
    const float* __restrict__ query_item,
    const float* __restrict__ K_lba, const float* __restrict__ V_lba,
    const float* __restrict__ l1_w, const float* __restrict__ l1_b,
    const float* __restrict__ l2_w, const float* __restrict__ l2_b,
    const float* __restrict__ gated_weight, const float* __restrict__ gated_bias,
    float* __restrict__ out)
{
    extern __shared__ float sm[];
    float* s_x   = sm + O_X;
    float* s_b1  = sm + O_B1;
    float* s_b2  = sm + O_B2;
    float* s_sc  = sm + O_WS;
    float* s_pm  = sm + O_PM;
    float* s_scq = sm + O_SCQ;
    float* s_glo = sm + O_GLO;
    float* s_gf  = sm + O_GFIN;
    float* s_aie = sm + O_AIE;
    float* s_ms  = sm + O_MISC;

    const int b = blockIdx.x;
    const int tid = threadIdx.x;
    const int lane = tid & 31;
    const int warp = tid >> 5;

    if (tid < Lp)  s_pm[tid] = (tid < Ln) ? padding_mask[b * Ln + tid] : 0.0f;
    // zero padded rows 50,51 of x
    if (tid < 2 * XS) s_x[Ln * XS + tid] = 0.0f;
    __syncthreads();

    build_inputs(s_x, user_items, item_embedding, pos_embedding, s_pm, b, warp, lane);
    __syncthreads();

    // ---- transformer layers ----
    for (int s = 0; s < Sn; s++) {
        // Qx -> b1 and Kx -> b2 in one merged phase (416 tiles over 256 threads)
        for (int t = tid; t < 416; t += NT) {
            if (t < 208) gtile(s_b1, s_x, Q_sabs + s * Dn * Dn, t >> 4, t & 15);
            else { int u = t - 208; gtile(s_b2, s_x, K_sabs + s * Dn * Dn, u >> 4, u & 15); }
        }
        __syncthreads();

        // scores[q][k] = dot(Qx[q],Kx[k])/8, causal/key mask, * pm[q] -> ws (scalar; reg-lean)
        if (tid < 169) {
            int qp = tid / 13, kr = tid % 13;
            const float* Q0 = s_b1 + qp * 4 * XS;
            const float* K0 = s_b2 + kr * XS;
            float a[4][4];
#pragma unroll
            for (int j = 0; j < 4; j++)
#pragma unroll
                for (int m = 0; m < 4; m++) a[j][m] = 0.0f;
#pragma unroll 4
            for (int d4 = 0; d4 < 16; d4++) {
                float4 qv[4], kv[4];
#pragma unroll
                for (int j = 0; j < 4; j++) qv[j] = *(const float4*)(Q0 + j * XS + d4 * 4);
#pragma unroll
                for (int m = 0; m < 4; m++) kv[m] = *(const float4*)(K0 + m * 13 * XS + d4 * 4);
#pragma unroll
                for (int j = 0; j < 4; j++)
#pragma unroll
                    for (int m = 0; m < 4; m++) {
                        a[j][m] += qv[j].x * kv[m].x;
                        a[j][m] += qv[j].y * kv[m].y;
                        a[j][m] += qv[j].z * kv[m].z;
                        a[j][m] += qv[j].w * kv[m].w;
                    }
            }
#pragma unroll
            for (int j = 0; j < 4; j++) {
                int q = qp * 4 + j;
#pragma unroll
                for (int m = 0; m < 4; m++) {
                    int k = kr + 13 * m;
                    float v;
                    if (q >= Ln || k >= Ln) v = 0.0f;
                    else {
                        v = a[j][m] * 0.125f;
                        if (k > q) v = NEGV;
                        if (s_pm[k] == 0.0f) v = NEGV;
                        v *= s_pm[q];
                    }
                    s_sc[q * SCS + k] = v;
                }
            }
        }
        __syncthreads();

        gemm44_xw(s_b1, s_x, V_sabs + s * Dn * Dn, tid);   __syncthreads();  // Vx -> b1 (Qx dead)

        // att = scores @ Vx + x -> b2 (Kx dead), then LN
        if (tid < 208) {
            int rp = tid >> 4, c4 = tid & 15;
            u64 a[4][2];
#pragma unroll
            for (int j = 0; j < 4; j++) { a[j][0] = 0ull; a[j][1] = 0ull; }
            core52s(s_sc + rp * 4 * SCS, s_b1, c4, a);
#pragma unroll
            for (int j = 0; j < 4; j++) {
                int l = rp * 4 + j;
                const float* xr = s_x + l * XS + c4 * 4;
                float2 p0 = unpk(a[j][0]), p1 = unpk(a[j][1]);
                *(float4*)(s_b2 + l * XS + c4 * 4) =
                    make_float4(p0.x + xr[0], p0.y + xr[1], p1.x + xr[2], p1.y + xr[3]);
            }
        }
        __syncthreads();
        ln_rows(s_b2, warp, lane);   // att in b2
        __syncthreads();

        // h = relu(c1p @ att + c1_b) -> b1 (c1p global, L1-resident, no staging)
        if (tid < 208) {
            int rp = tid >> 4, c4 = tid & 15;
            u64 a[4][2];
#pragma unroll
            for (int j = 0; j < 4; j++) { a[j][0] = 0ull; a[j][1] = 0ull; }
            core52g(g_c1p[s] + rp * 4 * Lp, s_b2, c4, a);
#pragma unroll
            for (int j = 0; j < 4; j++) {
                int l = rp * 4 + j;
                float4 r;
                if (l < Ln) {
                    float bb = __ldg(c1_b + s * Ln + l);
                    float2 p0 = unpk(a[j][0]), p1 = unpk(a[j][1]);
                    r = make_float4(fmaxf(p0.x + bb, 0.f), fmaxf(p0.y + bb, 0.f),
                                    fmaxf(p1.x + bb, 0.f), fmaxf(p1.y + bb, 0.f));
                } else r = make_float4(0.f, 0.f, 0.f, 0.f);
                *(float4*)(s_b1 + l * XS + c4 * 4) = r;
            }
        }
        __syncthreads();

        // ff = c2p @ h + c2_b + att, * pm -> x, then LN
        if (tid < 208) {
            int rp = tid >> 4, c4 = tid & 15;
            u64 a[4][2];
#pragma unroll
            for (int j = 0; j < 4; j++) { a[j][0] = 0ull; a[j][1] = 0ull; }
            core52g(g_c2p[s] + rp * 4 * Lp, s_b1, c4, a);
#pragma unroll
            for (int j = 0; j < 4; j++) {
                int l = rp * 4 + j;
                float4 r;
                if (l < Ln) {
                    float bb = __ldg(c2_b + s * Ln + l);
                    float pmv = s_pm[l];
                    const float* at = s_b2 + l * XS + c4 * 4;
                    float2 p0 = unpk(a[j][0]), p1 = unpk(a[j][1]);
                    r = make_float4((p0.x + bb + at[0]) * pmv, (p0.y + bb + at[1]) * pmv,
                                    (p1.x + bb + at[2]) * pmv, (p1.y + bb + at[3]) * pmv);
                } else r = make_float4(0.f, 0.f, 0.f, 0.f);
                *(float4*)(s_x + l * XS + c4 * 4) = r;
            }
        }
        __syncthreads();
        ln_rows(s_x, warp, lane);
        __syncthreads();
    }

    // ---- rebuild post-LN inputs into b1 (embeddings L2/L1-resident) ----
    if (tid < 2 * XS) s_b1[Ln * XS + tid] = 0.0f;
    __syncthreads();
    build_inputs(s_b1, user_items, item_embedding, pos_embedding, s_pm, b, warp, lane);
    __syncthreads();

    // ---- LBA head ----
    gemm44_xw(s_b2, s_b1, K_lba, tid);  __syncthreads();   // Kx -> b2

    // sc[l] = dot(query, Kx[l]); key-mask
    {
        float qv0 = __ldg(query_item + lane), qv1 = __ldg(query_item + lane + 32);
        for (int l = warp; l < Ln; l += 8) {
            float r = qv0 * s_b2[l * XS + lane] + qv1 * s_b2[l * XS + lane + 32];
            r = wredsum(r);
            if (s_pm[l] == 0.0f) r = NEGV;
            if (lane == 0) s_scq[l] = r;
        }
    }
    __syncthreads();

    // softmax over L (warp 0)
    if (warp == 0) {
        float v0 = (lane < Ln) ? s_scq[lane] : -3.4e38f;
        float v1 = (lane + 32 < Ln) ? s_scq[lane + 32] : -3.4e38f;
        float m = wredmax(fmaxf(v0, v1));
        float e0 = (lane < Ln) ? expf(v0 - m) : 0.0f;
        float e1 = (lane + 32 < Ln) ? expf(v1 - m) : 0.0f;
        float ssum = wredsum(e0 + e1);
        float inv = 1.0f / ssum;
        if (lane < Ln) s_scq[lane] = e0 * inv;
        if (lane + 32 < Ln) s_scq[lane + 32] = e1 * inv;
    }
    __syncthreads();

    gemm44_xw(s_b2, s_b1, V_lba, tid);  __syncthreads();   // Vx -> b2 (Kx dead)

    // glo[d] = sum_l p[l] * Vx[l][d]
    if (tid < Dn) {
        float a = 0.0f;
#pragma unroll 5
        for (int l = 0; l < Ln; l++) a += s_scq[l] * s_b2[l * XS + tid];
        s_glo[tid] = a;
    }
    __syncthreads();

    // LN -> MLP -> residual -> LN -> gfin; a_glo = dot(gfin, w1)+bias (warp 0)
    if (warp == 0) {
        float g0 = s_glo[lane], g1 = s_glo[lane + 32];
        float mu = wredsum(g0 + g1) * (1.0f / Dn);
        g0 -= mu; g1 -= mu;
        float var = wredsum(g0 * g0 + g1 * g1) * (1.0f / Dn);
        float inv = rsqrtf(var + 1e-8f);
        g0 *= inv; g1 *= inv;
        float w1v = l1_w[0], b1v = l1_b[0], w2v = l2_w[0], b2v = l2_b[0];
        float h0 = fmaxf(w1v * g0 + b1v, 0.0f);
        float h1 = fmaxf(w1v * g1 + b1v, 0.0f);
        float f0 = w2v * h0 + b2v + g0;
        float f1 = w2v * h1 + b2v + g1;
        mu = wredsum(f0 + f1) * (1.0f / Dn);
        f0 -= mu; f1 -= mu;
        var = wredsum(f0 * f0 + f1 * f1) * (1.0f / Dn);
        inv = rsqrtf(var + 1e-8f);
        f0 *= inv; f1 *= inv;
        s_gf[lane] = f0; s_gf[lane + 32] = f1;
        float r = wredsum(f0 * __ldg(gated_weight + 64 + lane) + f1 * __ldg(gated_weight + 96 + lane));
        if (lane == 0) s_ms[0] = r + gated_bias[0];
    }

    // a_ie[l] = dot(ie_raw[l], w0)
    {
        float gw0 = __ldg(gated_weight + lane), gw32 = __ldg(gated_weight + 32 + lane);
        for (int l = warp; l < Ln; l += 8) {
            int idx = user_items[b * Ln + l];
            float r = item_embedding[idx * Dn + lane] * gw0
                    + item_embedding[idx * Dn + lane + 32] * gw32;
            r = wredsum(r);
            if (lane == 0) s_aie[l] = r;
        }
    }
    __syncthreads();

    // ---- gating + output LN + dot with pos_e / neg_e ----
    float base_glo = s_ms[0];
    float gf0 = s_gf[lane], gf1 = s_gf[lane + 32];
    float gw128 = __ldg(gated_weight + 128 + lane);
    float gw160 = __ldg(gated_weight + 160 + lane);
    for (int l = warp; l < Ln; l += 8) {
        float xv0 = s_x[l * XS + lane], xv1 = s_x[l * XS + lane + 32];
        float pmv = s_pm[l];
        float base = s_aie[l] + base_glo;
#pragma unroll
        for (int br = 0; br < 2; br++) {
            const int* items = br ? neg_items : pos_items;
            int idx = items[b * Ln + l];
            float m0 = item_embedding[idx * Dn + lane];
            float m1 = item_embedding[idx * Dn + lane + 32];
            float dm = wredsum(m0 * gw128 + m1 * gw160);
            float logit = base + dm;
            float g = sigm(sigm(logit));
            float o0 = (xv0 * g + gf0 * (1.0f - g)) * pmv;
            float o1 = (xv1 * g + gf1 * (1.0f - g)) * pmv;
            float mu = wredsum(o0 + o1) * (1.0f / Dn);
            o0 -= mu; o1 -= mu;
            float var = wredsum(o0 * o0 + o1 * o1) * (1.0f / Dn);
            float inv = rsqrtf(var + 1e-8f);
            float r = wredsum((o0 * m0 + o1 * m1) * inv);
            if (lane == 0) out[br * (Bn * Ln) + b * Ln + l] = r;
        }
    }
}

extern "C" void kernel_launch(void* const* d_in, const int* in_sizes, int n_in,
                              void* d_out, int out_size) {
    const int*   user_items     = (const int*)d_in[0];
    const int*   pos_items      = (const int*)d_in[1];
    const int*   neg_items      = (const int*)d_in[2];
    const float* padding_mask   = (const float*)d_in[3];
    const float* item_embedding = (const float*)d_in[4];
    const float* pos_embedding  = (const float*)d_in[5];
    const float* Q_sabs         = (const float*)d_in[6];
    const float* K_sabs         = (const float*)d_in[7];
    const float* V_sabs         = (const float*)d_in[8];
    const float* c1_w           = (const float*)d_in[9];
    const float* c1_b           = (const float*)d_in[10];
    const float* c2_w           = (const float*)d_in[11];
    const float* c2_b           = (const float*)d_in[12];
    const float* query_item     = (const float*)d_in[13];
    const float* K_lba          = (const float*)d_in[14];
    const float* V_lba          = (const float*)d_in[15];
    const float* l1_w           = (const float*)d_in[16];
    const float* l1_b           = (const float*)d_in[17];
    const float* l2_w           = (const float*)d_in[18];
    const float* l2_b           = (const float*)d_in[19];
    const float* gated_weight   = (const float*)d_in[20];
    const float* gated_bias     = (const float*)d_in[21];

    prep_kernel<<<(Sn * Lp * Lp + 255) / 256, 256>>>(c1_w, c2_w);

    size_t smem = SMEM_FLOATS * sizeof(float);
    cudaFuncSetAttribute(fissa_kernel, cudaFuncAttributeMaxDynamicSharedMemorySize, (int)smem);
    fissa_kernel<<<Bn, NT, smem>>>(
        user_items, pos_items, neg_items, padding_mask, item_embedding, pos_embedding,
        Q_sabs, K_sabs, V_sabs, c1_b, c2_b, query_item, K_lba, V_lba,
        l1_w, l1_b, l2_w, l2_b, gated_weight, gated_bias, (float*)d_out);
}

// round 11
// speedup vs baseline: 1.3215x; 1.0152x over previous
#include <cuda_runtime.h>

#define Bn 1024
#define Ln 50
#define Lp 52      // padded row count
#define Dn 64
#define Sn 2
#define XS 68      // row stride (floats) for Lp x D activation arrays (16B-aligned, 4*XS%32==16)
#define SCS 52     // row stride for the padded 52x52 score matrix
#define NT 256
#define NEGV -4294967296.0f   // float(-2**32+1) after fp32 rounding (matches JAX)

// ---- shared memory layout (float offsets) ----
#define O_X     0       // running x                      52*68 = 3536
#define O_B1    3536    // Qx -> Vx/h -> inputs(lba)
#define O_B2    7072    // Kx -> att -> Kx_lba -> Vx_lba
#define O_WS    10608   // scores 52x52 = 2704
#define O_PM    13312   // padding mask (52)
#define O_SCQ   13364   // lba scores / softmax probs (64)
#define O_GFIN  13428   // final glo (64)
#define O_AIE   13492   // dot(ie, w0) per row (56)
#define O_MISC  13548   // scalars (16)
#define SMEM_FLOATS 13564   // 54.3 KB -> 4 CTAs/SM

typedef unsigned long long u64;

// zero-padded 52x52 copies of c1_w / c2_w, built once per launch by prep_kernel
__device__ float g_c1p[Sn][Lp * Lp];
__device__ float g_c2p[Sn][Lp * Lp];

__global__ void prep_kernel(const float* __restrict__ c1_w, const float* __restrict__ c2_w) {
    int i = blockIdx.x * blockDim.x + threadIdx.x;
    if (i < Sn * Lp * Lp) {
        int s = i / (Lp * Lp);
        int rc = i % (Lp * Lp);
        int r = rc / Lp, c = rc % Lp;
        float v1 = (r < Ln && c < Ln) ? c1_w[s * Ln * Ln + r * Ln + c] : 0.0f;
        float v2 = (r < Ln && c < Ln) ? c2_w[s * Ln * Ln + r * Ln + c] : 0.0f;
        g_c1p[s][rc] = v1;
        g_c2p[s][rc] = v2;
    }
}

// packed fp32x2 fma: acc = a*b + acc
__device__ __forceinline__ void fma2(u64& acc, u64 a, u64 b) {
    asm("fma.rn.f32x2 %0, %1, %2, %0;" : "+l"(acc) : "l"(a), "l"(b));
}
__device__ __forceinline__ u64 bcast(float x) {
    u64 r;
    asm("mov.b64 %0, {%1, %1};" : "=l"(r) : "r"(__float_as_uint(x)));
    return r;
}
__device__ __forceinline__ float2 unpk(u64 v) {
    unsigned int lo, hi;
    asm("mov.b64 {%0, %1}, %2;" : "=r"(lo), "=r"(hi) : "l"(v));
    return make_float2(__uint_as_float(lo), __uint_as_float(hi));
}

__device__ __forceinline__ float wredsum(float v) {
#pragma unroll
    for (int o = 16; o; o >>= 1) v += __shfl_xor_sync(0xffffffffu, v, o);
    return v;
}
__device__ __forceinline__ float wredmax(float v) {
#pragma unroll
    for (int o = 16; o; o >>= 1) v = fmaxf(v, __shfl_xor_sync(0xffffffffu, v, o));
    return v;
}
// fused 2-value full-warp reduction (independent chains interleave -> half latency)
__device__ __forceinline__ void wred2(float& s, float& q) {
#pragma unroll
    for (int o = 16; o; o >>= 1) {
        s += __shfl_xor_sync(0xffffffffu, s, o);
        q += __shfl_xor_sync(0xffffffffu, q, o);
    }
}
// fused 2-value reduction within 16-lane groups
__device__ __forceinline__ void red16_2(float& s, float& q, unsigned mask) {
#pragma unroll
    for (int o = 1; o <= 8; o <<= 1) {
        s += __shfl_xor_sync(mask, s, o);
        q += __shfl_xor_sync(mask, q, o);
    }
}
__device__ __forceinline__ float sigm(float x) { return 1.0f / (1.0f + expf(-x)); }

// one 4x4 output tile of out = xin(Lp x D smem, stride XS) @ w(DxD global row-major)
// f32x2 packed over output columns: acc u64[4][2].
__device__ __forceinline__ void gtile(float* __restrict__ out, const float* __restrict__ xin,
                                      const float* __restrict__ w, int rp, int c4) {
    const float* x0 = xin + rp * 4 * XS;
    u64 a[4][2];
#pragma unroll
    for (int j = 0; j < 4; j++) { a[j][0] = 0ull; a[j][1] = 0ull; }
#pragma unroll 4
    for (int k4 = 0; k4 < 16; k4++) {
        float4 xv[4];
#pragma unroll
        for (int j = 0; j < 4; j++)
            xv[j] = *(const float4*)(x0 + j * XS + k4 * 4);
#pragma unroll
        for (int kk = 0; kk < 4; kk++) {
            ulonglong2 wv = __ldg((const ulonglong2*)(w + (k4 * 4 + kk) * Dn + c4 * 4));
#pragma unroll
            for (int j = 0; j < 4; j++) {
                u64 xb = bcast(((const float*)&xv[j])[kk]);
                fma2(a[j][0], xb, wv.x);
                fma2(a[j][1], xb, wv.y);
            }
        }
    }
#pragma unroll
    for (int j = 0; j < 4; j++) {
        float2 p0 = unpk(a[j][0]), p1 = unpk(a[j][1]);
        *(float4*)(out + (rp * 4 + j) * XS + c4 * 4) = make_float4(p0.x, p0.y, p1.x, p1.y);
    }
}

// core: acc += A(4 rows GLOBAL, stride Lp, inner 52) x B(52 x D smem, stride XS)
__device__ __forceinline__ void core52g(const float* __restrict__ A0,
                                        const float* __restrict__ Bm, int c4, u64 a[4][2]) {
#pragma unroll 4
    for (int k4 = 0; k4 < 13; k4++) {
        float4 wv[4];
#pragma unroll
        for (int j = 0; j < 4; j++)
            wv[j] = __ldg((const float4*)(A0 + j * Lp + k4 * 4));
#pragma unroll
        for (int kk = 0; kk < 4; kk++) {
            ulonglong2 bv = *(const ulonglong2*)(Bm + (k4 * 4 + kk) * XS + c4 * 4);
#pragma unroll
            for (int j = 0; j < 4; j++) {
                u64 ab = bcast(((const float*)&wv[j])[kk]);
                fma2(a[j][0], ab, bv.x);
                fma2(a[j][1], ab, bv.y);
            }
        }
    }
}

// core with A in smem (scores), stride SCS
__device__ __forceinline__ void core52s(const float* __restrict__ A0,
                                        const float* __restrict__ Bm, int c4, u64 a[4][2]) {
#pragma unroll 4
    for (int k4 = 0; k4 < 13; k4++) {
        float4 wv[4];
#pragma unroll
        for (int j = 0; j < 4; j++)
            wv[j] = *(const float4*)(A0 + j * SCS + k4 * 4);
#pragma unroll
        for (int kk = 0; kk < 4; kk++) {
            ulonglong2 bv = *(const ulonglong2*)(Bm + (k4 * 4 + kk) * XS + c4 * 4);
#pragma unroll
            for (int j = 0; j < 4; j++) {
                u64 ab = bcast(((const float*)&wv[j])[kk]);
                fma2(a[j][0], ab, bv.x);
                fma2(a[j][1], ab, bv.y);
            }
        }
    }
}

// embed + pos + mask + LN -> dst (rows 0..49); single-pass mean/var
__device__ __forceinline__ void build_inputs(float* dst, const int* __restrict__ user_items,
                                             const float* __restrict__ item_embedding,
                                             const float* __restrict__ pos_embedding,
                                             const float* s_pm, int b, int warp, int lane) {
    for (int l = warp; l < Ln; l += 8) {
        int idx = user_items[b * Ln + l];
        float v0 = item_embedding[idx * Dn + lane]      + pos_embedding[l * Dn + lane];
        float v1 = item_embedding[idx * Dn + lane + 32] + pos_embedding[l * Dn + lane + 32];
        float pmv = s_pm[l];
        v0 *= pmv; v1 *= pmv;
        float s = v0 + v1, q = v0 * v0 + v1 * v1;
        wred2(s, q);
        float mu = s * (1.0f / Dn);
        float var = fmaxf(q * (1.0f / Dn) - mu * mu, 0.0f);
        float inv = rsqrtf(var + 1e-8f);
        dst[l * XS + lane] = (v0 - mu) * inv;
        dst[l * XS + lane + 32] = (v1 - mu) * inv;
    }
}

__global__ void __launch_bounds__(NT, 4) fissa_kernel(
    const int* __restrict__ user_items, const int* __restrict__ pos_items,
    const int* __restrict__ neg_items, const float* __restrict__ padding_mask,
    const float* __restrict__ item_embedding, const float* __restrict__ pos_embedding,
    const float* __restrict__ Q_sabs, const float* __restrict__ K_sabs,
    const float* __restrict__ V_sabs,
    const float* __restrict__ c1_b, const float* __restrict__ c2_b,
    const float* __restrict__ query_item,
    const float* __restrict__ K_lba, const float* __restrict__ V_lba,
    const float* __restrict__ l1_w, const float* __restrict__ l1_b,
    const float* __restrict__ l2_w, const float* __restrict__ l2_b,
    const float* __restrict__ gated_weight, const float* __restrict__ gated_bias,
    float* __restrict__ out)
{
    extern __shared__ float sm[];
    float* s_x   = sm + O_X;
    float* s_b1  = sm + O_B1;
    float* s_b2  = sm + O_B2;
    float* s_sc  = sm + O_WS;
    float* s_pm  = sm + O_PM;
    float* s_scq = sm + O_SCQ;
    float* s_gf  = sm + O_GFIN;
    float* s_aie = sm + O_AIE;
    float* s_ms  = sm + O_MISC;

    const int b = blockIdx.x;
    const int tid = threadIdx.x;
    const int lane = tid & 31;
    const int warp = tid >> 5;

    if (tid < Lp)  s_pm[tid] = (tid < Ln) ? padding_mask[b * Ln + tid] : 0.0f;
    if (tid < 2 * XS) s_x[Ln * XS + tid] = 0.0f;   // zero pad rows of x
    __syncthreads();

    build_inputs(s_x, user_items, item_embedding, pos_embedding, s_pm, b, warp, lane);
    __syncthreads();

    // ---- transformer layers ----
    for (int s = 0; s < Sn; s++) {
        // Qx -> b1 and Kx -> b2 in one merged phase
        for (int t = tid; t < 416; t += NT) {
            if (t < 208) gtile(s_b1, s_x, Q_sabs + s * Dn * Dn, t >> 4, t & 15);
            else { int u = t - 208; gtile(s_b2, s_x, K_sabs + s * Dn * Dn, u >> 4, u & 15); }
        }
        __syncthreads();

        // scores[q][k] = dot(Qx[q],Kx[k])/8, causal/key mask, * pm[q] -> ws (scalar; reg-lean)
        if (tid < 169) {
            int qp = tid / 13, kr = tid % 13;
            const float* Q0 = s_b1 + qp * 4 * XS;
            const float* K0 = s_b2 + kr * XS;
            float a[4][4];
#pragma unroll
            for (int j = 0; j < 4; j++)
#pragma unroll
                for (int m = 0; m < 4; m++) a[j][m] = 0.0f;
#pragma unroll 4
            for (int d4 = 0; d4 < 16; d4++) {
                float4 qv[4], kv[4];
#pragma unroll
                for (int j = 0; j < 4; j++) qv[j] = *(const float4*)(Q0 + j * XS + d4 * 4);
#pragma unroll
                for (int m = 0; m < 4; m++) kv[m] = *(const float4*)(K0 + m * 13 * XS + d4 * 4);
#pragma unroll
                for (int j = 0; j < 4; j++)
#pragma unroll
                    for (int m = 0; m < 4; m++) {
                        a[j][m] += qv[j].x * kv[m].x;
                        a[j][m] += qv[j].y * kv[m].y;
                        a[j][m] += qv[j].z * kv[m].z;
                        a[j][m] += qv[j].w * kv[m].w;
                    }
            }
#pragma unroll
            for (int j = 0; j < 4; j++) {
                int q = qp * 4 + j;
#pragma unroll
                for (int m = 0; m < 4; m++) {
                    int k = kr + 13 * m;
                    float v;
                    if (q >= Ln || k >= Ln) v = 0.0f;
                    else {
                        v = a[j][m] * 0.125f;
                        if (k > q) v = NEGV;
                        if (s_pm[k] == 0.0f) v = NEGV;
                        v *= s_pm[q];
                    }
                    s_sc[q * SCS + k] = v;
                }
            }
        }
        __syncthreads();

        // Vx -> b1 (Qx dead)
        if (tid < 208) gtile(s_b1, s_x, V_sabs + s * Dn * Dn, tid >> 4, tid & 15);
        __syncthreads();

        // att = scores @ Vx + x, fused LN (half-warp reduce) -> b2 (Kx dead)
        if (tid < 208) {
            unsigned mask = (tid >= 192) ? 0x0000ffffu : 0xffffffffu;
            int rp = tid >> 4, c4 = tid & 15;
            u64 a[4][2];
#pragma unroll
            for (int j = 0; j < 4; j++) { a[j][0] = 0ull; a[j][1] = 0ull; }
            core52s(s_sc + rp * 4 * SCS, s_b1, c4, a);
#pragma unroll
            for (int j = 0; j < 4; j++) {
                int l = rp * 4 + j;
                const float* xr = s_x + l * XS + c4 * 4;
                float2 p0 = unpk(a[j][0]), p1 = unpk(a[j][1]);
                float v0 = p0.x + xr[0], v1 = p0.y + xr[1];
                float v2 = p1.x + xr[2], v3 = p1.y + xr[3];
                float sv = v0 + v1 + v2 + v3;
                float qv = v0 * v0 + v1 * v1 + v2 * v2 + v3 * v3;
                red16_2(sv, qv, mask);
                float mu = sv * (1.0f / Dn);
                float var = fmaxf(qv * (1.0f / Dn) - mu * mu, 0.0f);
                float inv = rsqrtf(var + 1e-8f);
                *(float4*)(s_b2 + l * XS + c4 * 4) =
                    make_float4((v0 - mu) * inv, (v1 - mu) * inv,
                                (v2 - mu) * inv, (v3 - mu) * inv);
            }
        }
        __syncthreads();

        // h = relu(c1p @ att + c1_b) -> b1
        if (tid < 208) {
            int rp = tid >> 4, c4 = tid & 15;
            u64 a[4][2];
#pragma unroll
            for (int j = 0; j < 4; j++) { a[j][0] = 0ull; a[j][1] = 0ull; }
            core52g(g_c1p[s] + rp * 4 * Lp, s_b2, c4, a);
#pragma unroll
            for (int j = 0; j < 4; j++) {
                int l = rp * 4 + j;
                float4 r;
                if (l < Ln) {
                    float bb = __ldg(c1_b + s * Ln + l);
                    float2 p0 = unpk(a[j][0]), p1 = unpk(a[j][1]);
                    r = make_float4(fmaxf(p0.x + bb, 0.f), fmaxf(p0.y + bb, 0.f),
                                    fmaxf(p1.x + bb, 0.f), fmaxf(p1.y + bb, 0.f));
                } else r = make_float4(0.f, 0.f, 0.f, 0.f);
                *(float4*)(s_b1 + l * XS + c4 * 4) = r;
            }
        }
        __syncthreads();

        // ff = c2p @ h + c2_b + att, * pm, fused LN -> x
        if (tid < 208) {
            unsigned mask = (tid >= 192) ? 0x0000ffffu : 0xffffffffu;
            int rp = tid >> 4, c4 = tid & 15;
            u64 a[4][2];
#pragma unroll
            for (int j = 0; j < 4; j++) { a[j][0] = 0ull; a[j][1] = 0ull; }
            core52g(g_c2p[s] + rp * 4 * Lp, s_b1, c4, a);
#pragma unroll
            for (int j = 0; j < 4; j++) {
                int l = rp * 4 + j;
                float bb = (l < Ln) ? __ldg(c2_b + s * Ln + l) : 0.0f;
                float pmv = s_pm[l];   // pad rows have pm=0 -> zeros
                const float* at = s_b2 + l * XS + c4 * 4;
                float2 p0 = unpk(a[j][0]), p1 = unpk(a[j][1]);
                float v0 = (p0.x + bb + at[0]) * pmv, v1 = (p0.y + bb + at[1]) * pmv;
                float v2 = (p1.x + bb + at[2]) * pmv, v3 = (p1.y + bb + at[3]) * pmv;
                float sv = v0 + v1 + v2 + v3;
                float qv = v0 * v0 + v1 * v1 + v2 * v2 + v3 * v3;
                red16_2(sv, qv, mask);
                float mu = sv * (1.0f / Dn);
                float var = fmaxf(qv * (1.0f / Dn) - mu * mu, 0.0f);
                float inv = rsqrtf(var + 1e-8f);
                *(float4*)(s_x + l * XS + c4 * 4) =
                    make_float4((v0 - mu) * inv, (v1 - mu) * inv,
                                (v2 - mu) * inv, (v3 - mu) * inv);
            }
        }
        __syncthreads();
    }

    // ---- rebuild post-LN inputs into b1 (b1 pad rows are 0 from h-phase guard) ----
    build_inputs(s_b1, user_items, item_embedding, pos_embedding, s_pm, b, warp, lane);
    __syncthreads();

    // ---- LBA head: Kx -> b2 (warps 0-6) + a_ie (warp 7) ----
    if (tid < 208) gtile(s_b2, s_b1, K_lba, tid >> 4, tid & 15);
    else if (warp == 7) {
        float gw0 = __ldg(gated_weight + lane), gw32 = __ldg(gated_weight + 32 + lane);
        for (int l = 0; l < Ln; l++) {
            int idx = user_items[b * Ln + l];
            float r = item_embedding[idx * Dn + lane] * gw0
                    + item_embedding[idx * Dn + lane + 32] * gw32;
            r = wredsum(r);
            if (lane == 0) s_aie[l] = r;
        }
    }
    __syncthreads();

    // sc[l] = dot(query, Kx[l]); key-mask
    {
        float qv0 = __ldg(query_item + lane), qv1 = __ldg(query_item + lane + 32);
        for (int l = warp; l < Ln; l += 8) {
            float r = qv0 * s_b2[l * XS + lane] + qv1 * s_b2[l * XS + lane + 32];
            r = wredsum(r);
            if (s_pm[l] == 0.0f) r = NEGV;
            if (lane == 0) s_scq[l] = r;
        }
    }
    __syncthreads();

    // Vx -> b2 (warps 0-6, Kx dead) + softmax over sc (warp 7)
    if (tid < 208) gtile(s_b2, s_b1, V_lba, tid >> 4, tid & 15);
    else if (warp == 7) {
        float v0 = (lane < Ln) ? s_scq[lane] : -3.4e38f;
        float v1 = (lane + 32 < Ln) ? s_scq[lane + 32] : -3.4e38f;
        float m = wredmax(fmaxf(v0, v1));
        float e0 = (lane < Ln) ? expf(v0 - m) : 0.0f;
        float e1 = (lane + 32 < Ln) ? expf(v1 - m) : 0.0f;
        float ssum = wredsum(e0 + e1);
        float inv = 1.0f / ssum;
        if (lane < Ln) s_scq[lane] = e0 * inv;
        if (lane + 32 < Ln) s_scq[lane + 32] = e1 * inv;
    }
    __syncthreads();

    // glo (in regs) -> LN -> MLP -> residual -> LN -> gfin ; all on warp 0
    if (warp == 0) {
        float g0 = 0.0f, g1 = 0.0f;
#pragma unroll 5
        for (int l = 0; l < Ln; l++) {
            float p = s_scq[l];
            g0 += p * s_b2[l * XS + lane];
            g1 += p * s_b2[l * XS + lane + 32];
        }
        float sv = g0 + g1, qv = g0 * g0 + g1 * g1;
        wred2(sv, qv);
        float mu = sv * (1.0f / Dn);
        float var = fmaxf(qv * (1.0f / Dn) - mu * mu, 0.0f);
        float inv = rsqrtf(var + 1e-8f);
        g0 = (g0 - mu) * inv; g1 = (g1 - mu) * inv;
        float w1v = l1_w[0], b1v = l1_b[0], w2v = l2_w[0], b2v = l2_b[0];
        float f0 = w2v * fmaxf(w1v * g0 + b1v, 0.0f) + b2v + g0;
        float f1 = w2v * fmaxf(w1v * g1 + b1v, 0.0f) + b2v + g1;
        sv = f0 + f1; qv = f0 * f0 + f1 * f1;
        wred2(sv, qv);
        mu = sv * (1.0f / Dn);
        var = fmaxf(qv * (1.0f / Dn) - mu * mu, 0.0f);
        inv = rsqrtf(var + 1e-8f);
        f0 = (f0 - mu) * inv; f1 = (f1 - mu) * inv;
        s_gf[lane] = f0; s_gf[lane + 32] = f1;
        float r = wredsum(f0 * __ldg(gated_weight + 64 + lane) + f1 * __ldg(gated_weight + 96 + lane));
        if (lane == 0) s_ms[0] = r + gated_bias[0];
    }
    __syncthreads();

    // ---- gating + output LN + dot with pos_e / neg_e ----
    float base_glo = s_ms[0];
    float gf0 = s_gf[lane], gf1 = s_gf[lane + 32];
    float gw128 = __ldg(gated_weight + 128 + lane);
    float gw160 = __ldg(gated_weight + 160 + lane);
    for (int l = warp; l < Ln; l += 8) {
        float xv0 = s_x[l * XS + lane], xv1 = s_x[l * XS + lane + 32];
        float pmv = s_pm[l];
        float base = s_aie[l] + base_glo;
#pragma unroll
        for (int br = 0; br < 2; br++) {
            const int* items = br ? neg_items : pos_items;
            int idx = items[b * Ln + l];
            float m0 = item_embedding[idx * Dn + lane];
            float m1 = item_embedding[idx * Dn + lane + 32];
            float dm = wredsum(m0 * gw128 + m1 * gw160);
            float logit = base + dm;
            float g = sigm(sigm(logit));
            float o0 = (xv0 * g + gf0 * (1.0f - g)) * pmv;
            float o1 = (xv1 * g + gf1 * (1.0f - g)) * pmv;
            float sv = o0 + o1, qv = o0 * o0 + o1 * o1;
            wred2(sv, qv);
            float mu = sv * (1.0f / Dn);
            float var = fmaxf(qv * (1.0f / Dn) - mu * mu, 0.0f);
            float inv = rsqrtf(var + 1e-8f);
            float r = wredsum((o0 - mu) * m0 + (o1 - mu) * m1) * inv;
            if (lane == 0) out[br * (Bn * Ln) + b * Ln + l] = r;
        }
    }
}

extern "C" void kernel_launch(void* const* d_in, const int* in_sizes, int n_in,
                              void* d_out, int out_size) {
    const int*   user_items     = (const int*)d_in[0];
    const int*   pos_items      = (const int*)d_in[1];
    const int*   neg_items      = (const int*)d_in[2];
    const float* padding_mask   = (const float*)d_in[3];
    const float* item_embedding = (const float*)d_in[4];
    const float* pos_embedding  = (const float*)d_in[5];
    const float* Q_sabs         = (const float*)d_in[6];
    const float* K_sabs         = (const float*)d_in[7];
    const float* V_sabs         = (const float*)d_in[8];
    const float* c1_w           = (const float*)d_in[9];
    const float* c1_b           = (const float*)d_in[10];
    const float* c2_w           = (const float*)d_in[11];
    const float* c2_b           = (const float*)d_in[12];
    const float* query_item     = (const float*)d_in[13];
    const float* K_lba          = (const float*)d_in[14];
    const float* V_lba          = (const float*)d_in[15];
    const float* l1_w           = (const float*)d_in[16];
    const float* l1_b           = (const float*)d_in[17];
    const float* l2_w           = (const float*)d_in[18];
    const float* l2_b           = (const float*)d_in[19];
    const float* gated_weight   = (const float*)d_in[20];
    const float* gated_bias     = (const float*)d_in[21];

    prep_kernel<<<(Sn * Lp * Lp + 255) / 256, 256>>>(c1_w, c2_w);

    size_t smem = SMEM_FLOATS * sizeof(float);
    cudaFuncSetAttribute(fissa_kernel, cudaFuncAttributeMaxDynamicSharedMemorySize, (int)smem);
    fissa_kernel<<<Bn, NT, smem>>>(
        user_items, pos_items, neg_items, padding_mask, item_embedding, pos_embedding,
        Q_sabs, K_sabs, V_sabs, c1_b, c2_b, query_item, K_lba, V_lba,
        l1_w, l1_b, l2_w, l2_b, gated_weight, gated_bias, (float*)d_out);
}